// round 5
// baseline (speedup 1.0000x reference)
#include <cuda_runtime.h>
#include <math.h>

#define NMAX 100000
#define EMAX 1600000
#define HEADS 4
#define HID 32
#define F1 128
#define IN_NODE 12
#define IN_GLB 11
#define IN1 23
#define EDGE_DIM 5
#define DEC_IN 69
#define DEC_H1 64
#define DEC_H2 32
#define DEC_OUT 4

__device__ float g_g[NMAX * F1];
__device__ float g_h1[NMAX * F1];
__device__ float g_pa[NMAX * DEC_H1];
__device__ float g_pb[NMAX * DEC_H1];
__device__ float g_als[NMAX * HEADS];
__device__ float g_ald[NMAX * HEADS];
__device__ int   g_cnt[NMAX];
__device__ int   g_off[NMAX + 1];
__device__ int   g_cur[NMAX];
__device__ int   g_srcs[EMAX];
__device__ int   g_bsum[128];
__device__ float g_t1[F1];
__device__ float g_w1tt[IN_NODE * F1];
__device__ float g_w2t[DEC_H1 * DEC_H2];

__device__ __forceinline__ float lrelu02(float x) { return x > 0.f ? x : 0.2f * x; }
__device__ __forceinline__ float eluf(float x)    { return x > 0.f ? x : expm1f(x); }

// ---- packed f32x2 helpers ---------------------------------------------------
__device__ __forceinline__ unsigned long long pk2(float lo, float hi) {
    unsigned long long r;
    asm("mov.b64 %0, {%1, %2};" : "=l"(r) : "f"(lo), "f"(hi));
    return r;
}
__device__ __forceinline__ void fma2(unsigned long long& d, unsigned long long a,
                                     unsigned long long b) {
    asm("fma.rn.f32x2 %0, %1, %2, %0;" : "+l"(d) : "l"(a), "l"(b));
}
__device__ __forceinline__ float2 upk2(unsigned long long v) {
    float2 f;
    asm("mov.b64 {%0, %1}, %2;" : "=f"(f.x), "=f"(f.y) : "l"(v));
    return f;
}

// ---------------- prep ------------------------------------------------------
__global__ void k_prep(const float* __restrict__ u, const float* __restrict__ W1,
                       const float* __restrict__ dw2) {
    int tid = threadIdx.x;
    if (tid < F1) {
        float s = 0.f;
        #pragma unroll
        for (int k = 0; k < IN_GLB; k++) s += u[k] * W1[tid * IN1 + IN_NODE + k];
        g_t1[tid] = s;
    }
    for (int i = tid; i < IN_NODE * F1; i += blockDim.x) {
        int k = i >> 7, f = i & 127;
        g_w1tt[i] = W1[f * IN1 + k];
    }
    for (int i = tid; i < DEC_H1 * DEC_H2; i += blockDim.x) {
        int k = i >> 5, o = i & 31;
        g_w2t[i] = dw2[o * DEC_H1 + k];
    }
}

// ---------------- layer-1 node transform + attention logits ----------------
__global__ void k_gemm1(const float* __restrict__ x,
                        const float* __restrict__ asrc, const float* __restrict__ adst,
                        int N) {
    int n0 = blockIdx.x * 4;
    int f = threadIdx.x;
    __shared__ float xs[4][IN_NODE];
    if (f < 4 * IN_NODE) {
        int i = f / IN_NODE, k = f - i * IN_NODE;
        int n = n0 + i;
        xs[i][k] = (n < N) ? x[n * IN_NODE + k] : 0.f;
    }
    __syncthreads();
    float acc[4];
    float t = g_t1[f];
    #pragma unroll
    for (int i = 0; i < 4; i++) acc[i] = t;
    #pragma unroll
    for (int k = 0; k < IN_NODE; k++) {
        float w = g_w1tt[k * F1 + f];
        #pragma unroll
        for (int i = 0; i < 4; i++) acc[i] += xs[i][k] * w;
    }
    int h = f >> 5;
    float cas = asrc[f], cad = adst[f];
    #pragma unroll
    for (int i = 0; i < 4; i++) {
        int n = n0 + i;
        if (n >= N) break;
        g_g[n * F1 + f] = acc[i];
        float vs = acc[i] * cas, vd = acc[i] * cad;
        #pragma unroll
        for (int o = 16; o; o >>= 1) {
            vs += __shfl_xor_sync(0xffffffffu, vs, o);
            vd += __shfl_xor_sync(0xffffffffu, vd, o);
        }
        if ((f & 31) == 0) {
            g_als[n * HEADS + h] = vs;
            g_ald[n * HEADS + h] = vd;
        }
    }
}

// ---------------- layer-2 node transform (16 nodes/block, packed FMA) ------
#define G2N 16
__global__ __launch_bounds__(128) void k_gemm2(const float* __restrict__ W2,
                        const float* __restrict__ asrc, const float* __restrict__ adst,
                        int N) {
    int n0 = blockIdx.x * G2N;
    int f = threadIdx.x;
    __shared__ __align__(16) float hst[F1][G2N];
    #pragma unroll
    for (int i = 0; i < G2N; i++) {
        int n = n0 + i;
        hst[f][i] = (n < N) ? g_h1[n * F1 + f] : 0.f;
    }
    __syncthreads();
    unsigned long long acc2[8];
    #pragma unroll
    for (int p = 0; p < 8; p++) acc2[p] = 0ull;
    const float4* wrow = reinterpret_cast<const float4*>(W2 + f * F1);
    #pragma unroll 4
    for (int kq = 0; kq < F1 / 4; kq++) {
        float4 wv = wrow[kq];
        #pragma unroll
        for (int kk = 0; kk < 4; kk++) {
            float w = (kk == 0) ? wv.x : (kk == 1) ? wv.y : (kk == 2) ? wv.z : wv.w;
            unsigned long long ws = pk2(w, w);
            int k = kq * 4 + kk;
            const ulonglong2* hp = reinterpret_cast<const ulonglong2*>(&hst[k][0]);
            #pragma unroll
            for (int p = 0; p < 4; p++) {
                ulonglong2 hv = hp[p];
                fma2(acc2[p * 2], hv.x, ws);
                fma2(acc2[p * 2 + 1], hv.y, ws);
            }
        }
    }
    float acc[G2N];
    #pragma unroll
    for (int p = 0; p < 8; p++) {
        float2 t = upk2(acc2[p]);
        acc[p * 2] = t.x;
        acc[p * 2 + 1] = t.y;
    }
    int h = f >> 5;
    float cas = asrc[f], cad = adst[f];
    #pragma unroll
    for (int i = 0; i < G2N; i++) {
        int n = n0 + i;
        if (n >= N) break;
        g_g[n * F1 + f] = acc[i];
        float vs = acc[i] * cas, vd = acc[i] * cad;
        #pragma unroll
        for (int o = 16; o; o >>= 1) {
            vs += __shfl_xor_sync(0xffffffffu, vs, o);
            vd += __shfl_xor_sync(0xffffffffu, vd, o);
        }
        if ((f & 31) == 0) {
            g_als[n * HEADS + h] = vs;
            g_ald[n * HEADS + h] = vd;
        }
    }
}

// ---------------- CSR build --------------------------------------------------
__global__ void k_zero(int N) {
    int i = blockIdx.x * blockDim.x + threadIdx.x;
    if (i < N) g_cnt[i] = 0;
}
__global__ void k_hist(const int* __restrict__ dst, int M) {
    int e = blockIdx.x * blockDim.x + threadIdx.x;
    if (e < M) atomicAdd(&g_cnt[dst[e]], 1);
}
__global__ void k_scan1(int N) {
    __shared__ int sh[1024];
    int tid = threadIdx.x;
    int i = blockIdx.x * 1024 + tid;
    int v = (i < N) ? g_cnt[i] : 0;
    sh[tid] = v;
    __syncthreads();
    for (int o = 1; o < 1024; o <<= 1) {
        int t = (tid >= o) ? sh[tid - o] : 0;
        __syncthreads();
        sh[tid] += t;
        __syncthreads();
    }
    if (i < N) g_off[i] = sh[tid] - v;
    if (tid == 1023) g_bsum[blockIdx.x] = sh[1023];
}
__global__ void k_scan3(int nb, int N, int M) {
    __shared__ int sh[128];
    int tid = threadIdx.x;
    if (tid < 128) {
        int v = (tid < nb) ? g_bsum[tid] : 0;
        sh[tid] = v;
    }
    __syncthreads();
    if (tid < 128) {
        for (int o = 1; o < 128; o <<= 1) {
            int t = (tid >= o) ? sh[tid - o] : 0;
            __syncthreads();
            sh[tid] += t;
            __syncthreads();
        }
    } else {
        for (int o = 1; o < 128; o <<= 1) { __syncthreads(); __syncthreads(); }
    }
    int i = blockIdx.x * blockDim.x + tid;
    if (i < N) {
        int blk = i >> 10;
        int ex = (blk == 0) ? 0 : sh[blk - 1];
        int v = g_off[i] + ex;
        g_off[i] = v;
        g_cur[i] = v;
    }
    if (i == 0) g_off[N] = M;
}
__global__ void k_scatter(const int* __restrict__ src, const int* __restrict__ dst, int M) {
    int e = blockIdx.x * blockDim.x + threadIdx.x;
    if (e < M) {
        int d = dst[e];
        int p = atomicAdd(&g_cur[d], 1);
        g_srcs[p] = src[e];
    }
}

// ---------------- GAT aggregation: pipelined gather (MLP=4) -----------------
// concat==1 -> h1 = elu(v + b1); concat==0 -> mean heads, elu, then FUSED
// pa/pb precompute (pa = dw1[:, :32]@h2, pb = dw1[:, 32:64]@h2).
__global__ void k_agg(const float* __restrict__ bias, const float* __restrict__ dw1,
                      int concat, int N) {
    int n = blockIdx.x;
    if (n >= N) return;
    int h = threadIdx.x >> 5;
    int lane = threadIdx.x & 31;
    int beg = g_off[n], end = g_off[n + 1];

    float ad = g_ald[n * HEADS + h];
    float ws = __expf(lrelu02(g_als[n * HEADS + h] + ad));

    const float* gg = g_g + (h << 5) + lane;
    float acc = ws * gg[(size_t)n * F1];
    float psum = 0.f;
    for (int base = beg; base < end; base += 32) {
        int j = base + lane;
        float w = 0.f;
        int s = 0;
        if (j < end) {
            s = g_srcs[j];
            w = __expf(lrelu02(g_als[s * HEADS + h] + ad));
            psum += w;
        }
        int lim = min(32, end - base);
        int kk = 0;
        for (; kk + 4 <= lim; kk += 4) {
            float w0 = __shfl_sync(0xffffffffu, w, kk);
            float w1 = __shfl_sync(0xffffffffu, w, kk + 1);
            float w2 = __shfl_sync(0xffffffffu, w, kk + 2);
            float w3 = __shfl_sync(0xffffffffu, w, kk + 3);
            int s0 = __shfl_sync(0xffffffffu, s, kk);
            int s1 = __shfl_sync(0xffffffffu, s, kk + 1);
            int s2 = __shfl_sync(0xffffffffu, s, kk + 2);
            int s3 = __shfl_sync(0xffffffffu, s, kk + 3);
            float v0 = gg[(size_t)s0 * F1];
            float v1 = gg[(size_t)s1 * F1];
            float v2 = gg[(size_t)s2 * F1];
            float v3 = gg[(size_t)s3 * F1];
            acc += w0 * v0;
            acc += w1 * v1;
            acc += w2 * v2;
            acc += w3 * v3;
        }
        for (; kk < lim; kk++) {
            float wk = __shfl_sync(0xffffffffu, w, kk);
            int sk = __shfl_sync(0xffffffffu, s, kk);
            acc += wk * gg[(size_t)sk * F1];
        }
    }
    #pragma unroll
    for (int o = 16; o; o >>= 1) psum += __shfl_xor_sync(0xffffffffu, psum, o);
    float v = acc / (psum + ws);

    if (concat) {
        v += bias[(h << 5) + lane];
        g_h1[n * F1 + (h << 5) + lane] = eluf(v);
    } else {
        __shared__ float sm[F1];
        __shared__ float hrow[HID];
        sm[(h << 5) + lane] = v;
        __syncthreads();
        if (h == 0) {
            float t = (sm[lane] + sm[32 + lane] + sm[64 + lane] + sm[96 + lane]) * 0.25f
                      + bias[lane];
            hrow[lane] = eluf(t);
        }
        __syncthreads();
        // fused pa/pb: 128 threads -> (half = pa/pb, o in 0..63)
        int o = threadIdx.x & 63;
        int half = threadIdx.x >> 6;
        const float* wrow = dw1 + (size_t)o * DEC_IN + half * HID;
        float p = 0.f;
        #pragma unroll
        for (int k = 0; k < HID; k++) p += __ldg(wrow + k) * hrow[k];
        if (half == 0) g_pa[(size_t)n * DEC_H1 + o] = p;
        else           g_pb[(size_t)n * DEC_H1 + o] = p;
    }
}

// ---------------- decoder: 64-edge tiles, splat-packed GEMM2 ----------------
#define TB 64
#define ZS (TB + 4)
__global__ __launch_bounds__(256) void k_dec(
    const int* __restrict__ ei, const float* __restrict__ eattr,
    const float* __restrict__ dw1, const float* __restrict__ db1,
    const float* __restrict__ db2, const float* __restrict__ dw3,
    const float* __restrict__ db3, float* __restrict__ out, int M) {
    __shared__ __align__(16) unsigned long long sw2p[DEC_H1 * DEC_H2];  // (w,w) pairs
    __shared__ float sw3[DEC_H2 * DEC_OUT];
    __shared__ float sb2[DEC_H2];
    __shared__ float sb3[DEC_OUT];
    __shared__ float sw1c[EDGE_DIM * 64];
    __shared__ float sdb1[64];
    __shared__ int ssrc[TB], sdst[TB];
    __shared__ float eat[TB * EDGE_DIM];
    __shared__ __align__(16) float z1t[DEC_H1 * ZS];
    __shared__ __align__(16) float z2t[DEC_H2 * ZS];
    int tid = threadIdx.x;

    for (int i = tid; i < DEC_H1 * DEC_H2; i += 256) {
        float w = g_w2t[i];
        sw2p[i] = pk2(w, w);
    }
    if (tid < 128) sw3[tid] = dw3[tid];
    if (tid < 64)  sdb1[tid] = db1[tid];
    if (tid < 32)  sb2[tid] = db2[tid];
    if (tid < 4)   sb3[tid] = db3[tid];
    for (int i = tid; i < EDGE_DIM * 64; i += 256) {
        int k = i >> 6, o = i & 63;
        sw1c[i] = dw1[o * DEC_IN + 64 + k];
    }

    const int* srcp = ei;
    const int* dstp = ei + M;
    int ntiles = (M + TB - 1) / TB;
    int tx = tid & 15;
    int ty = tid >> 4;
    int o0 = tx * 2, e0 = ty * 4;

    for (int tile = blockIdx.x; tile < ntiles; tile += gridDim.x) {
        int eb = tile * TB;
        int nE = min(TB, M - eb);
        __syncthreads();
        if (tid < TB) {
            ssrc[tid] = (tid < nE) ? srcp[eb + tid] : 0;
            sdst[tid] = (tid < nE) ? dstp[eb + tid] : 0;
        }
        for (int i = tid; i < TB * EDGE_DIM; i += 256) {
            int gi = eb * EDGE_DIM + i;
            eat[i] = (gi < M * EDGE_DIM) ? eattr[gi] : 0.f;
        }
        __syncthreads();

        for (int i = tid; i < TB * 64; i += 256) {
            int e = i >> 6, o = i & 63;
            float v = g_pa[(size_t)ssrc[e] * 64 + o] + g_pb[(size_t)sdst[e] * 64 + o]
                      + sdb1[o];
            #pragma unroll
            for (int k = 0; k < EDGE_DIM; k++) v += sw1c[k * 64 + o] * eat[e * EDGE_DIM + k];
            z1t[o * ZS + e] = fmaxf(v, 0.f);
        }
        __syncthreads();

        // GEMM2: 4e x 2o per thread, K=64; no pack/splat movs in the loop
        unsigned long long a00 = 0ull, a01 = 0ull, a10 = 0ull, a11 = 0ull;
        #pragma unroll 8
        for (int k = 0; k < DEC_H1; k++) {
            ulonglong2 zp = *reinterpret_cast<const ulonglong2*>(&z1t[k * ZS + e0]);
            unsigned long long w0 = sw2p[k * DEC_H2 + o0];
            unsigned long long w1 = sw2p[k * DEC_H2 + o0 + 1];
            fma2(a00, zp.x, w0);
            fma2(a01, zp.x, w1);
            fma2(a10, zp.y, w0);
            fma2(a11, zp.y, w1);
        }
        {
            float b0 = sb2[o0], b1 = sb2[o0 + 1];
            float2 t00 = upk2(a00), t01 = upk2(a01), t10 = upk2(a10), t11 = upk2(a11);
            z2t[o0 * ZS + e0]           = fmaxf(t00.x + b0, 0.f);
            z2t[o0 * ZS + e0 + 1]       = fmaxf(t00.y + b0, 0.f);
            z2t[o0 * ZS + e0 + 2]       = fmaxf(t10.x + b0, 0.f);
            z2t[o0 * ZS + e0 + 3]       = fmaxf(t10.y + b0, 0.f);
            z2t[(o0 + 1) * ZS + e0]     = fmaxf(t01.x + b1, 0.f);
            z2t[(o0 + 1) * ZS + e0 + 1] = fmaxf(t01.y + b1, 0.f);
            z2t[(o0 + 1) * ZS + e0 + 2] = fmaxf(t11.x + b1, 0.f);
            z2t[(o0 + 1) * ZS + e0 + 3] = fmaxf(t11.y + b1, 0.f);
        }
        __syncthreads();

        {
            int e = tid & 63, o = tid >> 6;
            float acc = sb3[o];
            #pragma unroll
            for (int k = 0; k < DEC_H2; k++) acc += z2t[k * ZS + e] * sw3[o * DEC_H2 + k];
            if (e < nE) out[(eb + e) * DEC_OUT + o] = acc;
        }
    }
}

// ---------------- launch -----------------------------------------------------
extern "C" void kernel_launch(void* const* d_in, const int* in_sizes, int n_in,
                              void* d_out, int out_size) {
    const float* x     = (const float*)d_in[0];
    const int*   ei    = (const int*)d_in[1];
    const float* eattr = (const float*)d_in[2];
    const float* u     = (const float*)d_in[3];
    const float* W1    = (const float*)d_in[4];
    const float* as1   = (const float*)d_in[5];
    const float* ad1   = (const float*)d_in[6];
    const float* b1    = (const float*)d_in[7];
    const float* W2    = (const float*)d_in[8];
    const float* as2   = (const float*)d_in[9];
    const float* ad2   = (const float*)d_in[10];
    const float* b2    = (const float*)d_in[11];
    const float* dw1   = (const float*)d_in[12];
    const float* db1   = (const float*)d_in[13];
    const float* dw2   = (const float*)d_in[14];
    const float* db2   = (const float*)d_in[15];
    const float* dw3   = (const float*)d_in[16];
    const float* db3   = (const float*)d_in[17];
    float* out = (float*)d_out;

    int N = in_sizes[0] / IN_NODE;
    int M = in_sizes[1] / 2;
    if (N > NMAX || M > EMAX || N <= 0 || M <= 0) return;

    const int* srcp = ei;
    const int* dstp = ei + M;
    int nb = (N + 1023) / 1024;

    k_zero<<<(N + 255) / 256, 256>>>(N);
    k_prep<<<1, 256>>>(u, W1, dw2);
    k_hist<<<(M + 255) / 256, 256>>>(dstp, M);
    k_scan1<<<nb, 1024>>>(N);
    k_scan3<<<(N + 255) / 256, 256>>>(nb, N, M);
    k_scatter<<<(M + 255) / 256, 256>>>(srcp, dstp, M);

    k_gemm1<<<(N + 3) / 4, 128>>>(x, as1, ad1, N);
    k_agg<<<N, 128>>>(b1, dw1, 1, N);

    k_gemm2<<<(N + G2N - 1) / G2N, 128>>>(W2, as2, ad2, N);
    k_agg<<<N, 128>>>(b2, dw1, 0, N);

    k_dec<<<1184, 256>>>(ei, eattr, dw1, db1, db2, dw3, db3, out, M);
}

// round 6
// speedup vs baseline: 1.3368x; 1.3368x over previous
#include <cuda_runtime.h>
#include <math.h>

#define NMAX 100000
#define EMAX 1600000
#define HEADS 4
#define HID 32
#define F1 128
#define IN_NODE 12
#define IN_GLB 11
#define IN1 23
#define EDGE_DIM 5
#define DEC_IN 69
#define DEC_H1 64
#define DEC_H2 32
#define DEC_OUT 4

__device__ float g_g[NMAX * F1];
__device__ float g_h1[NMAX * F1];
__device__ float g_h2[NMAX * HID];
__device__ float g_pa[NMAX * DEC_H1];
__device__ float g_pb[NMAX * DEC_H1];
__device__ float g_als[NMAX * HEADS];
__device__ float g_ald[NMAX * HEADS];
__device__ int   g_cnt[NMAX];
__device__ int   g_off[NMAX + 1];
__device__ int   g_cur[NMAX];
__device__ int   g_srcs[EMAX];
__device__ int   g_bsum[128];
__device__ float g_t1[F1];
__device__ float g_w1tt[IN_NODE * F1];
__device__ float g_w2t[DEC_H1 * DEC_H2];

__device__ __forceinline__ float lrelu02(float x) { return x > 0.f ? x : 0.2f * x; }
__device__ __forceinline__ float eluf(float x)    { return x > 0.f ? x : expm1f(x); }

// ---- packed f32x2 helpers ---------------------------------------------------
__device__ __forceinline__ unsigned long long pk2(float lo, float hi) {
    unsigned long long r;
    asm("mov.b64 %0, {%1, %2};" : "=l"(r) : "f"(lo), "f"(hi));
    return r;
}
__device__ __forceinline__ void fma2(unsigned long long& d, unsigned long long a,
                                     unsigned long long b) {
    asm("fma.rn.f32x2 %0, %1, %2, %0;" : "+l"(d) : "l"(a), "l"(b));
}
__device__ __forceinline__ float2 upk2(unsigned long long v) {
    float2 f;
    asm("mov.b64 {%0, %1}, %2;" : "=f"(f.x), "=f"(f.y) : "l"(v));
    return f;
}

// ---------------- prep ------------------------------------------------------
__global__ void k_prep(const float* __restrict__ u, const float* __restrict__ W1,
                       const float* __restrict__ dw2) {
    int tid = threadIdx.x;
    if (tid < F1) {
        float s = 0.f;
        #pragma unroll
        for (int k = 0; k < IN_GLB; k++) s += u[k] * W1[tid * IN1 + IN_NODE + k];
        g_t1[tid] = s;
    }
    for (int i = tid; i < IN_NODE * F1; i += blockDim.x) {
        int k = i >> 7, f = i & 127;
        g_w1tt[i] = W1[f * IN1 + k];
    }
    for (int i = tid; i < DEC_H1 * DEC_H2; i += blockDim.x) {
        int k = i >> 5, o = i & 31;
        g_w2t[i] = dw2[o * DEC_H1 + k];
    }
}

// ---------------- layer-1 node transform + attention logits ----------------
__global__ void k_gemm1(const float* __restrict__ x,
                        const float* __restrict__ asrc, const float* __restrict__ adst,
                        int N) {
    int n0 = blockIdx.x * 4;
    int f = threadIdx.x;
    __shared__ float xs[4][IN_NODE];
    if (f < 4 * IN_NODE) {
        int i = f / IN_NODE, k = f - i * IN_NODE;
        int n = n0 + i;
        xs[i][k] = (n < N) ? x[n * IN_NODE + k] : 0.f;
    }
    __syncthreads();
    float acc[4];
    float t = g_t1[f];
    #pragma unroll
    for (int i = 0; i < 4; i++) acc[i] = t;
    #pragma unroll
    for (int k = 0; k < IN_NODE; k++) {
        float w = g_w1tt[k * F1 + f];
        #pragma unroll
        for (int i = 0; i < 4; i++) acc[i] += xs[i][k] * w;
    }
    int h = f >> 5;
    float cas = asrc[f], cad = adst[f];
    #pragma unroll
    for (int i = 0; i < 4; i++) {
        int n = n0 + i;
        if (n >= N) break;
        g_g[n * F1 + f] = acc[i];
        float vs = acc[i] * cas, vd = acc[i] * cad;
        #pragma unroll
        for (int o = 16; o; o >>= 1) {
            vs += __shfl_xor_sync(0xffffffffu, vs, o);
            vd += __shfl_xor_sync(0xffffffffu, vd, o);
        }
        if ((f & 31) == 0) {
            g_als[n * HEADS + h] = vs;
            g_ald[n * HEADS + h] = vd;
        }
    }
}

// ---------------- layer-2 node transform (16 nodes/block, packed FMA) ------
#define G2N 16
__global__ __launch_bounds__(128) void k_gemm2(const float* __restrict__ W2,
                        const float* __restrict__ asrc, const float* __restrict__ adst,
                        int N) {
    int n0 = blockIdx.x * G2N;
    int f = threadIdx.x;
    __shared__ __align__(16) float hst[F1][G2N];
    #pragma unroll
    for (int i = 0; i < G2N; i++) {
        int n = n0 + i;
        hst[f][i] = (n < N) ? g_h1[n * F1 + f] : 0.f;
    }
    __syncthreads();
    unsigned long long acc2[8];
    #pragma unroll
    for (int p = 0; p < 8; p++) acc2[p] = 0ull;
    const float4* wrow = reinterpret_cast<const float4*>(W2 + f * F1);
    #pragma unroll 4
    for (int kq = 0; kq < F1 / 4; kq++) {
        float4 wv = wrow[kq];
        #pragma unroll
        for (int kk = 0; kk < 4; kk++) {
            float w = (kk == 0) ? wv.x : (kk == 1) ? wv.y : (kk == 2) ? wv.z : wv.w;
            unsigned long long ws = pk2(w, w);
            int k = kq * 4 + kk;
            const ulonglong2* hp = reinterpret_cast<const ulonglong2*>(&hst[k][0]);
            #pragma unroll
            for (int p = 0; p < 4; p++) {
                ulonglong2 hv = hp[p];
                fma2(acc2[p * 2], hv.x, ws);
                fma2(acc2[p * 2 + 1], hv.y, ws);
            }
        }
    }
    float acc[G2N];
    #pragma unroll
    for (int p = 0; p < 8; p++) {
        float2 t = upk2(acc2[p]);
        acc[p * 2] = t.x;
        acc[p * 2 + 1] = t.y;
    }
    int h = f >> 5;
    float cas = asrc[f], cad = adst[f];
    #pragma unroll
    for (int i = 0; i < G2N; i++) {
        int n = n0 + i;
        if (n >= N) break;
        g_g[n * F1 + f] = acc[i];
        float vs = acc[i] * cas, vd = acc[i] * cad;
        #pragma unroll
        for (int o = 16; o; o >>= 1) {
            vs += __shfl_xor_sync(0xffffffffu, vs, o);
            vd += __shfl_xor_sync(0xffffffffu, vd, o);
        }
        if ((f & 31) == 0) {
            g_als[n * HEADS + h] = vs;
            g_ald[n * HEADS + h] = vd;
        }
    }
}

// ---------------- CSR build --------------------------------------------------
__global__ void k_zero(int N) {
    int i = blockIdx.x * blockDim.x + threadIdx.x;
    if (i < N) g_cnt[i] = 0;
}
__global__ void k_hist(const int* __restrict__ dst, int M) {
    int e = blockIdx.x * blockDim.x + threadIdx.x;
    if (e < M) atomicAdd(&g_cnt[dst[e]], 1);
}
__global__ void k_scan1(int N) {
    __shared__ int sh[1024];
    int tid = threadIdx.x;
    int i = blockIdx.x * 1024 + tid;
    int v = (i < N) ? g_cnt[i] : 0;
    sh[tid] = v;
    __syncthreads();
    for (int o = 1; o < 1024; o <<= 1) {
        int t = (tid >= o) ? sh[tid - o] : 0;
        __syncthreads();
        sh[tid] += t;
        __syncthreads();
    }
    if (i < N) g_off[i] = sh[tid] - v;
    if (tid == 1023) g_bsum[blockIdx.x] = sh[1023];
}
__global__ void k_scan3(int nb, int N, int M) {
    __shared__ int sh[128];
    int tid = threadIdx.x;
    if (tid < 128) {
        int v = (tid < nb) ? g_bsum[tid] : 0;
        sh[tid] = v;
    }
    __syncthreads();
    if (tid < 128) {
        for (int o = 1; o < 128; o <<= 1) {
            int t = (tid >= o) ? sh[tid - o] : 0;
            __syncthreads();
            sh[tid] += t;
            __syncthreads();
        }
    } else {
        for (int o = 1; o < 128; o <<= 1) { __syncthreads(); __syncthreads(); }
    }
    int i = blockIdx.x * blockDim.x + tid;
    if (i < N) {
        int blk = i >> 10;
        int ex = (blk == 0) ? 0 : sh[blk - 1];
        int v = g_off[i] + ex;
        g_off[i] = v;
        g_cur[i] = v;
    }
    if (i == 0) g_off[N] = M;
}
__global__ void k_scatter(const int* __restrict__ src, const int* __restrict__ dst, int M) {
    int e = blockIdx.x * blockDim.x + threadIdx.x;
    if (e < M) {
        int d = dst[e];
        int p = atomicAdd(&g_cur[d], 1);
        g_srcs[p] = src[e];
    }
}

// ---------------- GAT aggregation: pipelined gather (MLP=4), NO fusion ------
__global__ void k_agg(const float* __restrict__ bias, int concat, int N) {
    int n = blockIdx.x;
    if (n >= N) return;
    int h = threadIdx.x >> 5;
    int lane = threadIdx.x & 31;
    int beg = g_off[n], end = g_off[n + 1];

    float ad = g_ald[n * HEADS + h];
    float ws = __expf(lrelu02(g_als[n * HEADS + h] + ad));

    const float* gg = g_g + (h << 5) + lane;
    float acc = ws * gg[(size_t)n * F1];
    float psum = 0.f;
    for (int base = beg; base < end; base += 32) {
        int j = base + lane;
        float w = 0.f;
        int s = 0;
        if (j < end) {
            s = g_srcs[j];
            w = __expf(lrelu02(g_als[s * HEADS + h] + ad));
            psum += w;
        }
        int lim = min(32, end - base);
        int kk = 0;
        for (; kk + 4 <= lim; kk += 4) {
            float w0 = __shfl_sync(0xffffffffu, w, kk);
            float w1 = __shfl_sync(0xffffffffu, w, kk + 1);
            float w2 = __shfl_sync(0xffffffffu, w, kk + 2);
            float w3 = __shfl_sync(0xffffffffu, w, kk + 3);
            int s0 = __shfl_sync(0xffffffffu, s, kk);
            int s1 = __shfl_sync(0xffffffffu, s, kk + 1);
            int s2 = __shfl_sync(0xffffffffu, s, kk + 2);
            int s3 = __shfl_sync(0xffffffffu, s, kk + 3);
            float v0 = gg[(size_t)s0 * F1];
            float v1 = gg[(size_t)s1 * F1];
            float v2 = gg[(size_t)s2 * F1];
            float v3 = gg[(size_t)s3 * F1];
            acc += w0 * v0;
            acc += w1 * v1;
            acc += w2 * v2;
            acc += w3 * v3;
        }
        for (; kk < lim; kk++) {
            float wk = __shfl_sync(0xffffffffu, w, kk);
            int sk = __shfl_sync(0xffffffffu, s, kk);
            acc += wk * gg[(size_t)sk * F1];
        }
    }
    #pragma unroll
    for (int o = 16; o; o >>= 1) psum += __shfl_xor_sync(0xffffffffu, psum, o);
    float v = acc / (psum + ws);

    if (concat) {
        v += bias[(h << 5) + lane];
        g_h1[n * F1 + (h << 5) + lane] = eluf(v);
    } else {
        __shared__ float sm[F1];
        sm[(h << 5) + lane] = v;
        __syncthreads();
        if (h == 0) {
            float t = (sm[lane] + sm[32 + lane] + sm[64 + lane] + sm[96 + lane]) * 0.25f
                      + bias[lane];
            g_h2[n * HID + lane] = eluf(t);
        }
    }
}

// ---------------- decoder precompute: pa/pb (tiled, smem weights) -----------
__global__ __launch_bounds__(256) void k_pab(const float* __restrict__ dw1, int N) {
    __shared__ float sdw[64 * 65];
    __shared__ float sh2[16 * 32];
    int tid = threadIdx.x;
    for (int i = tid; i < 64 * 64; i += 256) {
        int o = i >> 6, k = i & 63;
        sdw[o * 65 + k] = dw1[o * DEC_IN + k];
    }
    int n0 = blockIdx.x * 16;
    for (int i = tid; i < 16 * 32; i += 256) {
        int nl = i >> 5, k = i & 31;
        int n = n0 + nl;
        sh2[i] = (n < N) ? g_h2[n * HID + k] : 0.f;
    }
    __syncthreads();
    int o = tid & 63, ng = tid >> 6;
    float pa[4] = {0.f, 0.f, 0.f, 0.f}, pb[4] = {0.f, 0.f, 0.f, 0.f};
    #pragma unroll
    for (int k = 0; k < 32; k++) {
        float wa = sdw[o * 65 + k];
        float wb = sdw[o * 65 + 32 + k];
        #pragma unroll
        for (int j = 0; j < 4; j++) {
            float hv = sh2[(ng * 4 + j) * 32 + k];
            pa[j] += wa * hv;
            pb[j] += wb * hv;
        }
    }
    #pragma unroll
    for (int j = 0; j < 4; j++) {
        int n = n0 + ng * 4 + j;
        if (n < N) {
            g_pa[n * 64 + o] = pa[j];
            g_pb[n * 64 + o] = pb[j];
        }
    }
}

// ---------------- decoder: 64-edge tiles, splat-packed GEMM2 ----------------
#define TB 64
#define ZS (TB + 4)
__global__ __launch_bounds__(256) void k_dec(
    const int* __restrict__ ei, const float* __restrict__ eattr,
    const float* __restrict__ dw1, const float* __restrict__ db1,
    const float* __restrict__ db2, const float* __restrict__ dw3,
    const float* __restrict__ db3, float* __restrict__ out, int M) {
    __shared__ __align__(16) unsigned long long sw2p[DEC_H1 * DEC_H2];
    __shared__ float sw3[DEC_H2 * DEC_OUT];
    __shared__ float sb2[DEC_H2];
    __shared__ float sb3[DEC_OUT];
    __shared__ float sw1c[EDGE_DIM * 64];
    __shared__ float sdb1[64];
    __shared__ int ssrc[TB], sdst[TB];
    __shared__ float eat[TB * EDGE_DIM];
    __shared__ __align__(16) float z1t[DEC_H1 * ZS];
    __shared__ __align__(16) float z2t[DEC_H2 * ZS];
    int tid = threadIdx.x;

    for (int i = tid; i < DEC_H1 * DEC_H2; i += 256) {
        float w = g_w2t[i];
        sw2p[i] = pk2(w, w);
    }
    if (tid < 128) sw3[tid] = dw3[tid];
    if (tid < 64)  sdb1[tid] = db1[tid];
    if (tid < 32)  sb2[tid] = db2[tid];
    if (tid < 4)   sb3[tid] = db3[tid];
    for (int i = tid; i < EDGE_DIM * 64; i += 256) {
        int k = i >> 6, o = i & 63;
        sw1c[i] = dw1[o * DEC_IN + 64 + k];
    }

    const int* srcp = ei;
    const int* dstp = ei + M;
    int ntiles = (M + TB - 1) / TB;
    int tx = tid & 15;
    int ty = tid >> 4;
    int o0 = tx * 2, e0 = ty * 4;

    for (int tile = blockIdx.x; tile < ntiles; tile += gridDim.x) {
        int eb = tile * TB;
        int nE = min(TB, M - eb);
        __syncthreads();
        if (tid < TB) {
            ssrc[tid] = (tid < nE) ? srcp[eb + tid] : 0;
            sdst[tid] = (tid < nE) ? dstp[eb + tid] : 0;
        }
        for (int i = tid; i < TB * EDGE_DIM; i += 256) {
            int gi = eb * EDGE_DIM + i;
            eat[i] = (gi < M * EDGE_DIM) ? eattr[gi] : 0.f;
        }
        __syncthreads();

        for (int i = tid; i < TB * 64; i += 256) {
            int e = i >> 6, o = i & 63;
            float v = g_pa[(size_t)ssrc[e] * 64 + o] + g_pb[(size_t)sdst[e] * 64 + o]
                      + sdb1[o];
            #pragma unroll
            for (int k = 0; k < EDGE_DIM; k++) v += sw1c[k * 64 + o] * eat[e * EDGE_DIM + k];
            z1t[o * ZS + e] = fmaxf(v, 0.f);
        }
        __syncthreads();

        unsigned long long a00 = 0ull, a01 = 0ull, a10 = 0ull, a11 = 0ull;
        #pragma unroll 8
        for (int k = 0; k < DEC_H1; k++) {
            ulonglong2 zp = *reinterpret_cast<const ulonglong2*>(&z1t[k * ZS + e0]);
            unsigned long long w0 = sw2p[k * DEC_H2 + o0];
            unsigned long long w1 = sw2p[k * DEC_H2 + o0 + 1];
            fma2(a00, zp.x, w0);
            fma2(a01, zp.x, w1);
            fma2(a10, zp.y, w0);
            fma2(a11, zp.y, w1);
        }
        {
            float b0 = sb2[o0], b1 = sb2[o0 + 1];
            float2 t00 = upk2(a00), t01 = upk2(a01), t10 = upk2(a10), t11 = upk2(a11);
            z2t[o0 * ZS + e0]           = fmaxf(t00.x + b0, 0.f);
            z2t[o0 * ZS + e0 + 1]       = fmaxf(t00.y + b0, 0.f);
            z2t[o0 * ZS + e0 + 2]       = fmaxf(t10.x + b0, 0.f);
            z2t[o0 * ZS + e0 + 3]       = fmaxf(t10.y + b0, 0.f);
            z2t[(o0 + 1) * ZS + e0]     = fmaxf(t01.x + b1, 0.f);
            z2t[(o0 + 1) * ZS + e0 + 1] = fmaxf(t01.y + b1, 0.f);
            z2t[(o0 + 1) * ZS + e0 + 2] = fmaxf(t11.x + b1, 0.f);
            z2t[(o0 + 1) * ZS + e0 + 3] = fmaxf(t11.y + b1, 0.f);
        }
        __syncthreads();

        {
            int e = tid & 63, o = tid >> 6;
            float acc = sb3[o];
            #pragma unroll
            for (int k = 0; k < DEC_H2; k++) acc += z2t[k * ZS + e] * sw3[o * DEC_H2 + k];
            if (e < nE) out[(eb + e) * DEC_OUT + o] = acc;
        }
    }
}

// ---------------- launch -----------------------------------------------------
extern "C" void kernel_launch(void* const* d_in, const int* in_sizes, int n_in,
                              void* d_out, int out_size) {
    const float* x     = (const float*)d_in[0];
    const int*   ei    = (const int*)d_in[1];
    const float* eattr = (const float*)d_in[2];
    const float* u     = (const float*)d_in[3];
    const float* W1    = (const float*)d_in[4];
    const float* as1   = (const float*)d_in[5];
    const float* ad1   = (const float*)d_in[6];
    const float* b1    = (const float*)d_in[7];
    const float* W2    = (const float*)d_in[8];
    const float* as2   = (const float*)d_in[9];
    const float* ad2   = (const float*)d_in[10];
    const float* b2    = (const float*)d_in[11];
    const float* dw1   = (const float*)d_in[12];
    const float* db1   = (const float*)d_in[13];
    const float* dw2   = (const float*)d_in[14];
    const float* db2   = (const float*)d_in[15];
    const float* dw3   = (const float*)d_in[16];
    const float* db3   = (const float*)d_in[17];
    float* out = (float*)d_out;

    int N = in_sizes[0] / IN_NODE;
    int M = in_sizes[1] / 2;
    if (N > NMAX || M > EMAX || N <= 0 || M <= 0) return;

    const int* srcp = ei;
    const int* dstp = ei + M;
    int nb = (N + 1023) / 1024;

    k_zero<<<(N + 255) / 256, 256>>>(N);
    k_prep<<<1, 256>>>(u, W1, dw2);
    k_hist<<<(M + 255) / 256, 256>>>(dstp, M);
    k_scan1<<<nb, 1024>>>(N);
    k_scan3<<<(N + 255) / 256, 256>>>(nb, N, M);
    k_scatter<<<(M + 255) / 256, 256>>>(srcp, dstp, M);

    k_gemm1<<<(N + 3) / 4, 128>>>(x, as1, ad1, N);
    k_agg<<<N, 128>>>(b1, 1, N);

    k_gemm2<<<(N + G2N - 1) / G2N, 128>>>(W2, as2, ad2, N);
    k_agg<<<N, 128>>>(b2, 0, N);

    k_pab<<<(N + 15) / 16, 256>>>(dw1, N);
    k_dec<<<1184, 256>>>(ei, eattr, dw1, db1, db2, dw3, db3, out, M);
}